// round 4
// baseline (speedup 1.0000x reference)
#include <cuda_runtime.h>
#include <math.h>

#define NMAX 100000
#define FEAT 64

// Scratch (device globals — the sanctioned workaround for no-alloc rule)
__device__ float g_dinv[NMAX];            // deg, then rsqrt(deg)
__device__ float g_h[NMAX * FEAT];        // pre-aggregation features (x @ W)
__device__ float g_agg[NMAX * FEAT];      // neighbor aggregation accumulator
__device__ float g_act[NMAX * FEAT];      // post-relu layer output

// ---------------------------------------------------------------------------
// Degree pipeline  (edge_index is int32: JAX demotes int64 under default x64=off)
// ---------------------------------------------------------------------------
__global__ void k_init_deg(int n) {
    int i = blockIdx.x * blockDim.x + threadIdx.x;
    if (i < n) g_dinv[i] = 1.0f;   // self-loop
}

__global__ void k_deg(const int* __restrict__ ei, int e) {
    int i = blockIdx.x * blockDim.x + threadIdx.x;
    if (i < e) atomicAdd(&g_dinv[ei[e + i]], 1.0f);  // dst row
}

__global__ void k_rsqrt(int n) {
    int i = blockIdx.x * blockDim.x + threadIdx.x;
    if (i < n) g_dinv[i] = rsqrtf(g_dinv[i]);
}

// ---------------------------------------------------------------------------
// GEMM: H = X @ W   (X: [n,64], W: [64,64])  also zeroes g_agg
// block = 256 threads, 64 nodes/block, thread computes 4x4 micro-tile
// ---------------------------------------------------------------------------
__global__ void k_gemm64(const float* __restrict__ X, const float* __restrict__ W,
                         int n, int use_act) {
    __shared__ float sW[64 * 64];
    __shared__ float sX[64 * 65];
    const float* Xp = use_act ? g_act : X;
    int t = threadIdx.x;
    int n0 = blockIdx.x * 64;

#pragma unroll
    for (int i = 0; i < 16; i++) sW[t + 256 * i] = W[t + 256 * i];
#pragma unroll
    for (int i = 0; i < 16; i++) {
        int idx = t + 256 * i;          // 0..4095
        int r = idx >> 6, c = idx & 63;
        sX[r * 65 + c] = (n0 + r < n) ? Xp[(size_t)(n0 + r) * 64 + c] : 0.0f;
    }
    __syncthreads();

    int tx = t & 15, ty = t >> 4;       // cols 4*tx.. , rows 4*ty..
    float acc[4][4];
#pragma unroll
    for (int i = 0; i < 4; i++)
#pragma unroll
        for (int j = 0; j < 4; j++) acc[i][j] = 0.0f;

#pragma unroll
    for (int k = 0; k < 64; k++) {
        float4 wv = *(const float4*)&sW[k * 64 + tx * 4];
#pragma unroll
        for (int i = 0; i < 4; i++) {
            float xv = sX[(ty * 4 + i) * 65 + k];
            acc[i][0] = fmaf(xv, wv.x, acc[i][0]);
            acc[i][1] = fmaf(xv, wv.y, acc[i][1]);
            acc[i][2] = fmaf(xv, wv.z, acc[i][2]);
            acc[i][3] = fmaf(xv, wv.w, acc[i][3]);
        }
    }

#pragma unroll
    for (int i = 0; i < 4; i++) {
        int r = n0 + ty * 4 + i;
        if (r < n) {
            *(float4*)&g_h[(size_t)r * 64 + tx * 4] =
                make_float4(acc[i][0], acc[i][1], acc[i][2], acc[i][3]);
            *(float4*)&g_agg[(size_t)r * 64 + tx * 4] = make_float4(0.f, 0.f, 0.f, 0.f);
        }
    }
}

// ---------------------------------------------------------------------------
// Edge scatter: agg[dst] += h[src] * dinv[src]*dinv[dst]
// 16 lanes per edge; lane c gathers one float4 (coalesced) and issues
// 4 scalar REDG.ADD.F32 to the destination row.
// ---------------------------------------------------------------------------
__global__ void k_scatter(const int* __restrict__ ei, int e) {
    int tid = blockIdx.x * blockDim.x + threadIdx.x;
    int edge = tid >> 4;
    if (edge >= e) return;
    int c = tid & 15;
    int s = ei[edge];
    int d = ei[edge + e];
    float coef = g_dinv[s] * g_dinv[d];
    float4 v = ((const float4*)g_h)[(size_t)s * 16 + c];
    float* p = g_agg + ((size_t)d * 64 + c * 4);
    atomicAdd(p + 0, v.x * coef);
    atomicAdd(p + 1, v.y * coef);
    atomicAdd(p + 2, v.z * coef);
    atomicAdd(p + 3, v.w * coef);
}

// ---------------------------------------------------------------------------
// Finalize: act = relu(agg + h * dinv^2 + b)
// ---------------------------------------------------------------------------
__global__ void k_finalize(const float* __restrict__ bias, int n) {
    int tid = blockIdx.x * blockDim.x + threadIdx.x;
    if (tid >= n * 16) return;
    int node = tid >> 4, c = tid & 15;
    float di = g_dinv[node];
    float di2 = di * di;
    float4 a = ((const float4*)g_agg)[tid];
    float4 h = ((const float4*)g_h)[tid];
    float4 bv = ((const float4*)bias)[c];
    float4 o;
    o.x = fmaxf(fmaf(h.x, di2, a.x) + bv.x, 0.0f);
    o.y = fmaxf(fmaf(h.y, di2, a.y) + bv.y, 0.0f);
    o.z = fmaxf(fmaf(h.z, di2, a.z) + bv.z, 0.0f);
    o.w = fmaxf(fmaf(h.w, di2, a.w) + bv.w, 0.0f);
    ((float4*)g_act)[tid] = o;
}

// ---------------------------------------------------------------------------
// FC head: out = act @ Wfc + bfc   (Wfc: [64,16])
// block = 256 threads, 16 nodes/block, thread computes one (node, col)
// ---------------------------------------------------------------------------
__global__ void k_fc(const float* __restrict__ W, const float* __restrict__ b,
                     float* __restrict__ out, int n) {
    __shared__ float sW[64 * 16];
    __shared__ float sX[16 * 65];
    __shared__ float sB[16];
    int t = threadIdx.x;
    if (t < 16) sB[t] = b[t];
#pragma unroll
    for (int i = 0; i < 4; i++) sW[t + 256 * i] = W[t + 256 * i];
    int n0 = blockIdx.x * 16;
#pragma unroll
    for (int i = 0; i < 4; i++) {
        int idx = t + 256 * i;          // 0..1023
        int r = idx >> 6, c = idx & 63;
        sX[r * 65 + c] = (n0 + r < n) ? g_act[(size_t)(n0 + r) * 64 + c] : 0.0f;
    }
    __syncthreads();

    int j = t & 15, r = t >> 4;
    float acc = sB[j];
#pragma unroll
    for (int k = 0; k < 64; k++)
        acc = fmaf(sX[r * 65 + k], sW[k * 16 + j], acc);
    int rg = n0 + r;
    if (rg < n) out[(size_t)rg * 16 + j] = acc;
}

// ---------------------------------------------------------------------------
extern "C" void kernel_launch(void* const* d_in, const int* in_sizes, int n_in,
                              void* d_out, int out_size) {
    const float* x   = (const float*)d_in[0];
    const int*   ei  = (const int*)d_in[1];   // int32! (JAX x64 disabled)
    const float* W1  = (const float*)d_in[2];
    const float* b1  = (const float*)d_in[3];
    const float* W2  = (const float*)d_in[4];
    const float* b2  = (const float*)d_in[5];
    const float* Wfc = (const float*)d_in[6];
    const float* bfc = (const float*)d_in[7];
    float* out = (float*)d_out;

    int n = in_sizes[0] / FEAT;
    int e = in_sizes[1] / 2;

    int nb_n   = (n + 255) / 256;
    int nb_e   = (e + 255) / 256;
    int nb_g   = (n + 63) / 64;
    int nb_sc  = (int)(((long long)e * 16 + 255) / 256);
    int nb_fin = (n * 16 + 255) / 256;
    int nb_fc  = (n + 15) / 16;

    // Degrees + normalization
    k_init_deg<<<nb_n, 256>>>(n);
    k_deg<<<nb_e, 256>>>(ei, e);
    k_rsqrt<<<nb_n, 256>>>(n);

    // Layer 1
    k_gemm64<<<nb_g, 256>>>(x, W1, n, 0);
    k_scatter<<<nb_sc, 256>>>(ei, e);
    k_finalize<<<nb_fin, 256>>>(b1, n);

    // Layer 2
    k_gemm64<<<nb_g, 256>>>(x, W2, n, 1);
    k_scatter<<<nb_sc, 256>>>(ei, e);
    k_finalize<<<nb_fin, 256>>>(b2, n);

    // FC head
    k_fc<<<nb_fc, 256>>>(Wfc, bfc, out, n);
}

// round 5
// speedup vs baseline: 2.8217x; 2.8217x over previous
#include <cuda_runtime.h>
#include <math.h>

#define NMAX 100000
#define EMAX 1600000
#define FEAT 64

// Scratch (device globals — the sanctioned workaround for no-alloc rule)
__device__ float g_dinv[NMAX];                       // rsqrt(deg)
__device__ int   g_count[NMAX];                      // in-degree histogram
__device__ int   g_cursor[NMAX];                     // placement cursors
__device__ int   g_start[NMAX];                      // CSR offsets (exclusive scan)
__device__ int   g_bsum[128];                        // scan block sums
__device__ int   g_srcs[EMAX];                       // CSR: src ids grouped by dst
__device__ __align__(16) float g_hs[NMAX * FEAT];    // (X@W) * dinv[row]
__device__ __align__(16) float g_act[NMAX * FEAT];   // post-relu layer output

// ---------------------------------------------------------------------------
// CSR build pipeline
// ---------------------------------------------------------------------------
__global__ void k_zero(int n) {
    int i = blockIdx.x * blockDim.x + threadIdx.x;
    if (i < n) { g_count[i] = 0; g_cursor[i] = 0; }
}

__global__ void k_hist(const int* __restrict__ ei, int e) {
    int i = blockIdx.x * blockDim.x + threadIdx.x;
    if (i < e) atomicAdd(&g_count[ei[e + i]], 1);   // dst row
}

__global__ void k_dinv(int n) {
    int i = blockIdx.x * blockDim.x + threadIdx.x;
    if (i < n) g_dinv[i] = rsqrtf((float)g_count[i] + 1.0f);
}

// Exclusive scan over g_count -> g_start (1024 elems/block)
__global__ void k_scan1(int n) {
    __shared__ int sh[1024];
    int t = threadIdx.x;
    int i = blockIdx.x * 1024 + t;
    int v = (i < n) ? g_count[i] : 0;
    sh[t] = v; __syncthreads();
#pragma unroll
    for (int off = 1; off < 1024; off <<= 1) {
        int a = (t >= off) ? sh[t - off] : 0;
        __syncthreads();
        sh[t] += a;
        __syncthreads();
    }
    if (i < n) g_start[i] = sh[t] - v;              // exclusive
    if (t == 1023) g_bsum[blockIdx.x] = sh[1023];   // block total
}

__global__ void k_scan2(int nb) {
    __shared__ int sh[128];
    int t = threadIdx.x;
    int v = (t < nb) ? g_bsum[t] : 0;
    sh[t] = v; __syncthreads();
#pragma unroll
    for (int off = 1; off < 128; off <<= 1) {
        int a = (t >= off) ? sh[t - off] : 0;
        __syncthreads();
        sh[t] += a;
        __syncthreads();
    }
    if (t < nb) g_bsum[t] = sh[t] - v;              // exclusive block offsets
}

__global__ void k_scan3(int n) {
    int i = blockIdx.x * blockDim.x + threadIdx.x;
    if (i < n) g_start[i] += g_bsum[i >> 10];
}

__global__ void k_place(const int* __restrict__ ei, int e) {
    int i = blockIdx.x * blockDim.x + threadIdx.x;
    if (i < e) {
        int s = ei[i];
        int d = ei[e + i];
        int pos = g_start[d] + atomicAdd(&g_cursor[d], 1);
        g_srcs[pos] = s;
    }
}

// ---------------------------------------------------------------------------
// GEMM: HS = (X @ W) * dinv[row]   (X: [n,64], W: [64,64])
// block = 256 threads, 64 nodes/block, thread computes 4x4 micro-tile
// ---------------------------------------------------------------------------
__global__ void k_gemm64(const float* __restrict__ X, const float* __restrict__ W,
                         int n, int use_act) {
    __shared__ float sW[64 * 64];
    __shared__ float sX[64 * 65];
    const float* Xp = use_act ? g_act : X;
    int t = threadIdx.x;
    int n0 = blockIdx.x * 64;

#pragma unroll
    for (int i = 0; i < 16; i++) sW[t + 256 * i] = W[t + 256 * i];
#pragma unroll
    for (int i = 0; i < 16; i++) {
        int idx = t + 256 * i;          // 0..4095
        int r = idx >> 6, c = idx & 63;
        sX[r * 65 + c] = (n0 + r < n) ? Xp[(size_t)(n0 + r) * 64 + c] : 0.0f;
    }
    __syncthreads();

    int tx = t & 15, ty = t >> 4;       // cols 4*tx.. , rows 4*ty..
    float acc[4][4];
#pragma unroll
    for (int i = 0; i < 4; i++)
#pragma unroll
        for (int j = 0; j < 4; j++) acc[i][j] = 0.0f;

#pragma unroll
    for (int k = 0; k < 64; k++) {
        float4 wv = *(const float4*)&sW[k * 64 + tx * 4];
#pragma unroll
        for (int i = 0; i < 4; i++) {
            float xv = sX[(ty * 4 + i) * 65 + k];
            acc[i][0] = fmaf(xv, wv.x, acc[i][0]);
            acc[i][1] = fmaf(xv, wv.y, acc[i][1]);
            acc[i][2] = fmaf(xv, wv.z, acc[i][2]);
            acc[i][3] = fmaf(xv, wv.w, acc[i][3]);
        }
    }

#pragma unroll
    for (int i = 0; i < 4; i++) {
        int r = n0 + ty * 4 + i;
        if (r < n) {
            float di = g_dinv[r];
            *(float4*)&g_hs[(size_t)r * 64 + tx * 4] =
                make_float4(acc[i][0] * di, acc[i][1] * di,
                            acc[i][2] * di, acc[i][3] * di);
        }
    }
}

// ---------------------------------------------------------------------------
// Fused gather + finalize:  act[d] = relu(dinv[d] * (hs[d] + sum_src hs[src]) + b)
// one warp per node; lane holds float2 slice of the 64-wide row
// ---------------------------------------------------------------------------
__global__ void k_gather(const float* __restrict__ bias, int n) {
    int warp = (blockIdx.x * blockDim.x + threadIdx.x) >> 5;
    if (warp >= n) return;
    int lane = threadIdx.x & 31;

    int start = g_start[warp];
    int deg   = g_count[warp];
    const int* __restrict__ srcs = g_srcs + start;
    const float2* __restrict__ hs2 = (const float2*)g_hs;

    float2 acc = hs2[(size_t)warp * 32 + lane];   // self-loop term (hs[d])

    int j = 0;
    int end4 = deg & ~3;
    for (; j < end4; j += 4) {
        int s0 = srcs[j + 0];
        int s1 = srcs[j + 1];
        int s2 = srcs[j + 2];
        int s3 = srcs[j + 3];
        float2 v0 = hs2[(size_t)s0 * 32 + lane];
        float2 v1 = hs2[(size_t)s1 * 32 + lane];
        float2 v2 = hs2[(size_t)s2 * 32 + lane];
        float2 v3 = hs2[(size_t)s3 * 32 + lane];
        acc.x += (v0.x + v1.x) + (v2.x + v3.x);
        acc.y += (v0.y + v1.y) + (v2.y + v3.y);
    }
    for (; j < deg; j++) {
        int s = srcs[j];
        float2 v = hs2[(size_t)s * 32 + lane];
        acc.x += v.x;
        acc.y += v.y;
    }

    float di = g_dinv[warp];
    float2 bv = ((const float2*)bias)[lane];
    float2 o;
    o.x = fmaxf(fmaf(acc.x, di, bv.x), 0.0f);
    o.y = fmaxf(fmaf(acc.y, di, bv.y), 0.0f);
    ((float2*)g_act)[(size_t)warp * 32 + lane] = o;
}

// ---------------------------------------------------------------------------
// FC head: out = act @ Wfc + bfc   (Wfc: [64,16])
// ---------------------------------------------------------------------------
__global__ void k_fc(const float* __restrict__ W, const float* __restrict__ b,
                     float* __restrict__ out, int n) {
    __shared__ float sW[64 * 16];
    __shared__ float sX[16 * 65];
    __shared__ float sB[16];
    int t = threadIdx.x;
    if (t < 16) sB[t] = b[t];
#pragma unroll
    for (int i = 0; i < 4; i++) sW[t + 256 * i] = W[t + 256 * i];
    int n0 = blockIdx.x * 16;
#pragma unroll
    for (int i = 0; i < 4; i++) {
        int idx = t + 256 * i;          // 0..1023
        int r = idx >> 6, c = idx & 63;
        sX[r * 65 + c] = (n0 + r < n) ? g_act[(size_t)(n0 + r) * 64 + c] : 0.0f;
    }
    __syncthreads();

    int j = t & 15, r = t >> 4;
    float acc = sB[j];
#pragma unroll
    for (int k = 0; k < 64; k++)
        acc = fmaf(sX[r * 65 + k], sW[k * 16 + j], acc);
    int rg = n0 + r;
    if (rg < n) out[(size_t)rg * 16 + j] = acc;
}

// ---------------------------------------------------------------------------
extern "C" void kernel_launch(void* const* d_in, const int* in_sizes, int n_in,
                              void* d_out, int out_size) {
    const float* x   = (const float*)d_in[0];
    const int*   ei  = (const int*)d_in[1];   // int32 (JAX x64 disabled)
    const float* W1  = (const float*)d_in[2];
    const float* b1  = (const float*)d_in[3];
    const float* W2  = (const float*)d_in[4];
    const float* b2  = (const float*)d_in[5];
    const float* Wfc = (const float*)d_in[6];
    const float* bfc = (const float*)d_in[7];
    float* out = (float*)d_out;

    int n = in_sizes[0] / FEAT;
    int e = in_sizes[1] / 2;

    int nb_n  = (n + 255) / 256;
    int nb_e  = (e + 255) / 256;
    int nb_g  = (n + 63) / 64;
    int nb_s1 = (n + 1023) / 1024;               // scan blocks (<=128)
    int nb_ga = (int)(((long long)n * 32 + 255) / 256);
    int nb_fc = (n + 15) / 16;

    // CSR build (once, reused by both layers)
    k_zero <<<nb_n, 256>>>(n);
    k_hist <<<nb_e, 256>>>(ei, e);
    k_dinv <<<nb_n, 256>>>(n);
    k_scan1<<<nb_s1, 1024>>>(n);
    k_scan2<<<1, 128>>>(nb_s1);
    k_scan3<<<nb_n, 256>>>(n);
    k_place<<<nb_e, 256>>>(ei, e);

    // Layer 1
    k_gemm64<<<nb_g, 256>>>(x, W1, n, 0);
    k_gather<<<nb_ga, 256>>>(b1, n);

    // Layer 2
    k_gemm64<<<nb_g, 256>>>(x, W2, n, 1);
    k_gather<<<nb_ga, 256>>>(b2, n);

    // FC head
    k_fc<<<nb_fc, 256>>>(Wfc, bfc, out, n);
}

// round 6
// speedup vs baseline: 2.8493x; 1.0098x over previous
#include <cuda_runtime.h>
#include <math.h>

#define NMAX 100000
#define EMAX 1600000
#define FEAT 64

// Scratch (device globals — the sanctioned workaround for no-alloc rule)
__device__ float g_dinv[NMAX];                       // rsqrt(deg)
__device__ int   g_count[NMAX];                      // in-degree histogram
__device__ int   g_cursor[NMAX];                     // placement cursors (init = start)
__device__ int   g_start[NMAX];                      // CSR offsets (exclusive scan)
__device__ int   g_bsum[128];                        // scan block sums
__device__ int   g_srcs[EMAX];                       // CSR: src ids grouped by dst
__device__ __align__(16) float g_hs[NMAX * FEAT];    // (X@W) * dinv[row]
__device__ __align__(16) float g_act[NMAX * FEAT];   // post-relu layer output

// ---------------------------------------------------------------------------
// CSR build pipeline
// ---------------------------------------------------------------------------
__global__ void k_zero(int n) {
    int i = blockIdx.x * blockDim.x + threadIdx.x;
    if (i < n) g_count[i] = 0;
}

__global__ void k_hist(const int* __restrict__ ei, int e) {
    int i = blockIdx.x * blockDim.x + threadIdx.x;
    if (i < e) atomicAdd(&g_count[ei[e + i]], 1);   // dst row
}

// Exclusive scan over g_count -> g_start (1024/block, shfl-based) + dinv fused
__global__ void k_scan1(int n) {
    __shared__ int wsum[32];
    int t = threadIdx.x;
    int i = blockIdx.x * 1024 + t;
    int v = (i < n) ? g_count[i] : 0;
    if (i < n) g_dinv[i] = rsqrtf((float)v + 1.0f);

    int lane = t & 31, w = t >> 5;
    int s = v;
#pragma unroll
    for (int off = 1; off < 32; off <<= 1) {
        int u = __shfl_up_sync(0xffffffff, s, off);
        if (lane >= off) s += u;
    }
    if (lane == 31) wsum[w] = s;
    __syncthreads();
    if (w == 0) {
        int ws = wsum[lane];
#pragma unroll
        for (int off = 1; off < 32; off <<= 1) {
            int u = __shfl_up_sync(0xffffffff, ws, off);
            if (lane >= off) ws += u;
        }
        wsum[lane] = ws;
    }
    __syncthreads();
    int excl = s - v + (w > 0 ? wsum[w - 1] : 0);
    if (i < n) g_start[i] = excl;
    if (t == 1023) g_bsum[blockIdx.x] = wsum[31];
}

__global__ void k_scan2(int nb) {
    __shared__ int sh[128];
    int t = threadIdx.x;
    int v = (t < nb) ? g_bsum[t] : 0;
    sh[t] = v; __syncthreads();
#pragma unroll
    for (int off = 1; off < 128; off <<= 1) {
        int a = (t >= off) ? sh[t - off] : 0;
        __syncthreads();
        sh[t] += a;
        __syncthreads();
    }
    if (t < nb) g_bsum[t] = sh[t] - v;              // exclusive block offsets
}

__global__ void k_scan3(int n) {
    int i = blockIdx.x * blockDim.x + threadIdx.x;
    if (i < n) {
        int st = g_start[i] + g_bsum[i >> 10];
        g_start[i]  = st;
        g_cursor[i] = st;                            // placement cursor = start
    }
}

__global__ void k_place(const int* __restrict__ ei, int e) {
    int i = blockIdx.x * blockDim.x + threadIdx.x;
    if (i < e) {
        int s = ei[i];
        int d = ei[e + i];
        g_srcs[atomicAdd(&g_cursor[d], 1)] = s;
    }
}

// ---------------------------------------------------------------------------
// GEMM: HS = (X @ W) * dinv[row]   (X: [n,64], W: [64,64])
// 256 threads, 128 rows/block, thread computes 8x4 micro-tile,
// k-loop unrolled x4 with float4 LDS on both operands.
// ---------------------------------------------------------------------------
__global__ void __launch_bounds__(256) k_gemm64(
        const float* __restrict__ X, const float* __restrict__ W,
        int n, int use_act) {
    __shared__ float  sW[64 * 64];                   // 16 KB
    __shared__ float4 sX4[128 * 16];                 // 32 KB (rows x 16 float4)
    const float* Xp = use_act ? g_act : X;
    int t = threadIdx.x;
    int n0 = blockIdx.x * 128;

#pragma unroll
    for (int i = 0; i < 16; i++) sW[t + 256 * i] = W[t + 256 * i];
    const float4* Xg4 = (const float4*)Xp;
#pragma unroll
    for (int i = 0; i < 8; i++) {
        int idx = t + 256 * i;                       // 0..2047
        int r = idx >> 4, c = idx & 15;
        sX4[idx] = (n0 + r < n) ? Xg4[(size_t)(n0 + r) * 16 + c]
                                : make_float4(0.f, 0.f, 0.f, 0.f);
    }
    __syncthreads();

    int tx = t & 15, ty = t >> 4;                    // cols 4*tx.., rows 8*ty..
    float acc[8][4];
#pragma unroll
    for (int i = 0; i < 8; i++)
#pragma unroll
        for (int j = 0; j < 4; j++) acc[i][j] = 0.0f;

#pragma unroll
    for (int k4 = 0; k4 < 16; k4++) {
        float4 w0 = *(const float4*)&sW[(k4 * 4 + 0) * 64 + tx * 4];
        float4 w1 = *(const float4*)&sW[(k4 * 4 + 1) * 64 + tx * 4];
        float4 w2 = *(const float4*)&sW[(k4 * 4 + 2) * 64 + tx * 4];
        float4 w3 = *(const float4*)&sW[(k4 * 4 + 3) * 64 + tx * 4];
#pragma unroll
        for (int i = 0; i < 8; i++) {
            float4 xv = sX4[(ty * 8 + i) * 16 + k4];
            acc[i][0] = fmaf(xv.x, w0.x, acc[i][0]);
            acc[i][1] = fmaf(xv.x, w0.y, acc[i][1]);
            acc[i][2] = fmaf(xv.x, w0.z, acc[i][2]);
            acc[i][3] = fmaf(xv.x, w0.w, acc[i][3]);
            acc[i][0] = fmaf(xv.y, w1.x, acc[i][0]);
            acc[i][1] = fmaf(xv.y, w1.y, acc[i][1]);
            acc[i][2] = fmaf(xv.y, w1.z, acc[i][2]);
            acc[i][3] = fmaf(xv.y, w1.w, acc[i][3]);
            acc[i][0] = fmaf(xv.z, w2.x, acc[i][0]);
            acc[i][1] = fmaf(xv.z, w2.y, acc[i][1]);
            acc[i][2] = fmaf(xv.z, w2.z, acc[i][2]);
            acc[i][3] = fmaf(xv.z, w2.w, acc[i][3]);
            acc[i][0] = fmaf(xv.w, w3.x, acc[i][0]);
            acc[i][1] = fmaf(xv.w, w3.y, acc[i][1]);
            acc[i][2] = fmaf(xv.w, w3.z, acc[i][2]);
            acc[i][3] = fmaf(xv.w, w3.w, acc[i][3]);
        }
    }

#pragma unroll
    for (int i = 0; i < 8; i++) {
        int r = n0 + ty * 8 + i;
        if (r < n) {
            float di = g_dinv[r];
            *(float4*)&g_hs[(size_t)r * 64 + tx * 4] =
                make_float4(acc[i][0] * di, acc[i][1] * di,
                            acc[i][2] * di, acc[i][3] * di);
        }
    }
}

// ---------------------------------------------------------------------------
// Fused gather + finalize:  act[d] = relu(dinv[d] * (hs[d] + sum_src hs[src]) + b)
// one warp per node; lane holds float2 slice; inner loop unrolled x8
// ---------------------------------------------------------------------------
__global__ void k_gather(const float* __restrict__ bias, int n) {
    int warp = (blockIdx.x * blockDim.x + threadIdx.x) >> 5;
    if (warp >= n) return;
    int lane = threadIdx.x & 31;

    int start = g_start[warp];
    int deg   = g_count[warp];
    const int* __restrict__ srcs = g_srcs + start;
    const float2* __restrict__ hs2 = (const float2*)g_hs;

    float2 acc = hs2[(size_t)warp * 32 + lane];      // self-loop term (hs[d])

    int j = 0;
    int end8 = deg & ~7;
    for (; j < end8; j += 8) {
        int s[8];
#pragma unroll
        for (int q = 0; q < 8; q++) s[q] = srcs[j + q];
        float2 v[8];
#pragma unroll
        for (int q = 0; q < 8; q++) v[q] = hs2[(size_t)s[q] * 32 + lane];
#pragma unroll
        for (int q = 0; q < 8; q++) { acc.x += v[q].x; acc.y += v[q].y; }
    }
    for (; j < deg; j++) {
        float2 v = hs2[(size_t)srcs[j] * 32 + lane];
        acc.x += v.x;
        acc.y += v.y;
    }

    float di = g_dinv[warp];
    float2 bv = ((const float2*)bias)[lane];
    float2 o;
    o.x = fmaxf(fmaf(acc.x, di, bv.x), 0.0f);
    o.y = fmaxf(fmaf(acc.y, di, bv.y), 0.0f);
    ((float2*)g_act)[(size_t)warp * 32 + lane] = o;
}

// ---------------------------------------------------------------------------
// FC head: out = act @ Wfc + bfc   (Wfc: [64,16])
// ---------------------------------------------------------------------------
__global__ void k_fc(const float* __restrict__ W, const float* __restrict__ b,
                     float* __restrict__ out, int n) {
    __shared__ float sW[64 * 16];
    __shared__ float sX[16 * 65];
    __shared__ float sB[16];
    int t = threadIdx.x;
    if (t < 16) sB[t] = b[t];
#pragma unroll
    for (int i = 0; i < 4; i++) sW[t + 256 * i] = W[t + 256 * i];
    int n0 = blockIdx.x * 16;
#pragma unroll
    for (int i = 0; i < 4; i++) {
        int idx = t + 256 * i;                       // 0..1023
        int r = idx >> 6, c = idx & 63;
        sX[r * 65 + c] = (n0 + r < n) ? g_act[(size_t)(n0 + r) * 64 + c] : 0.0f;
    }
    __syncthreads();

    int j = t & 15, r = t >> 4;
    float acc = sB[j];
#pragma unroll
    for (int k = 0; k < 64; k++)
        acc = fmaf(sX[r * 65 + k], sW[k * 16 + j], acc);
    int rg = n0 + r;
    if (rg < n) out[(size_t)rg * 16 + j] = acc;
}

// ---------------------------------------------------------------------------
extern "C" void kernel_launch(void* const* d_in, const int* in_sizes, int n_in,
                              void* d_out, int out_size) {
    const float* x   = (const float*)d_in[0];
    const int*   ei  = (const int*)d_in[1];   // int32 (JAX x64 disabled)
    const float* W1  = (const float*)d_in[2];
    const float* b1  = (const float*)d_in[3];
    const float* W2  = (const float*)d_in[4];
    const float* b2  = (const float*)d_in[5];
    const float* Wfc = (const float*)d_in[6];
    const float* bfc = (const float*)d_in[7];
    float* out = (float*)d_out;

    int n = in_sizes[0] / FEAT;
    int e = in_sizes[1] / 2;

    int nb_n  = (n + 255) / 256;
    int nb_e  = (e + 255) / 256;
    int nb_g  = (n + 127) / 128;
    int nb_s1 = (n + 1023) / 1024;               // scan blocks (<=128)
    int nb_ga = (int)(((long long)n * 32 + 255) / 256);
    int nb_fc = (n + 15) / 16;

    // CSR build (once, reused by both layers)
    k_zero <<<nb_n, 256>>>(n);
    k_hist <<<nb_e, 256>>>(ei, e);
    k_scan1<<<nb_s1, 1024>>>(n);
    k_scan2<<<1, 128>>>(nb_s1);
    k_scan3<<<nb_n, 256>>>(n);
    k_place<<<nb_e, 256>>>(ei, e);

    // Layer 1
    k_gemm64<<<nb_g, 256>>>(x, W1, n, 0);
    k_gather<<<nb_ga, 256>>>(b1, n);

    // Layer 2
    k_gemm64<<<nb_g, 256>>>(x, W2, n, 1);
    k_gather<<<nb_ga, 256>>>(b2, n);

    // FC head
    k_fc<<<nb_fc, 256>>>(Wfc, bfc, out, n);
}

// round 7
// speedup vs baseline: 2.9919x; 1.0500x over previous
#include <cuda_runtime.h>
#include <cuda_fp16.h>
#include <math.h>

#define NMAX 100000
#define EMAX 1600000
#define FEAT 64

// Scratch (device globals — the sanctioned workaround for no-alloc rule)
__device__ float  g_dinv[NMAX];                        // rsqrt(deg)
__device__ int    g_count[NMAX];                       // in-degree histogram
__device__ int    g_cursor[NMAX];                      // placement cursors (init = start)
__device__ int    g_start[NMAX];                       // CSR offsets (exclusive scan)
__device__ int    g_bsum[128];                         // scan block sums
__device__ int    g_srcs[EMAX];                        // CSR: src ids grouped by dst
__device__ __align__(16) __half g_hs[NMAX * FEAT];     // (X@W) * dinv[row], fp16
__device__ __align__(16) float  g_act[NMAX * FEAT];    // post-relu layer output

// ---------------------------------------------------------------------------
// CSR build pipeline
// ---------------------------------------------------------------------------
__global__ void k_zero(int n) {
    int i = blockIdx.x * blockDim.x + threadIdx.x;
    if (i < n) g_count[i] = 0;
}

__global__ void k_hist(const int* __restrict__ ei, int e) {
    int i = blockIdx.x * blockDim.x + threadIdx.x;
    if (i < e) atomicAdd(&g_count[ei[e + i]], 1);   // dst row
}

// Exclusive scan over g_count -> g_start (1024/block, shfl-based) + dinv fused
__global__ void k_scan1(int n) {
    __shared__ int wsum[32];
    int t = threadIdx.x;
    int i = blockIdx.x * 1024 + t;
    int v = (i < n) ? g_count[i] : 0;
    if (i < n) g_dinv[i] = rsqrtf((float)v + 1.0f);

    int lane = t & 31, w = t >> 5;
    int s = v;
#pragma unroll
    for (int off = 1; off < 32; off <<= 1) {
        int u = __shfl_up_sync(0xffffffff, s, off);
        if (lane >= off) s += u;
    }
    if (lane == 31) wsum[w] = s;
    __syncthreads();
    if (w == 0) {
        int ws = wsum[lane];
#pragma unroll
        for (int off = 1; off < 32; off <<= 1) {
            int u = __shfl_up_sync(0xffffffff, ws, off);
            if (lane >= off) ws += u;
        }
        wsum[lane] = ws;
    }
    __syncthreads();
    int excl = s - v + (w > 0 ? wsum[w - 1] : 0);
    if (i < n) g_start[i] = excl;
    if (t == 1023) g_bsum[blockIdx.x] = wsum[31];
}

// scan3 with fused block-offset reduction (replaces the old k_scan2 launch).
// Each 256-thread block covers indices [blk*256, blk*256+255], which all lie
// inside ONE 1024-wide scan1 window (since 256*blk mod 1024 + 255 < 1024),
// so the needed offset is sum of g_bsum[0 .. (blk>>2)-1] — one reduction.
__global__ void k_scan3(int n, int nb1) {
    __shared__ int red[8];
    __shared__ int s_off;
    int t = threadIdx.x;
    int blk_of = blockIdx.x >> 2;                    // scan1 window index

    int v = (t < nb1 && t < blk_of) ? g_bsum[t] : 0; // t in [0,128)
    if (t < 128) {
        int lane = t & 31, w = t >> 5;
#pragma unroll
        for (int off = 16; off > 0; off >>= 1)
            v += __shfl_down_sync(0xffffffff, v, off);
        if (lane == 0) red[w] = v;
    }
    __syncthreads();
    if (t == 0) s_off = red[0] + red[1] + red[2] + red[3];
    __syncthreads();

    int i = blockIdx.x * 256 + t;
    if (i < n) {
        int st = g_start[i] + s_off;
        g_start[i]  = st;
        g_cursor[i] = st;                            // placement cursor = start
    }
}

__global__ void k_place(const int* __restrict__ ei, int e) {
    int i = blockIdx.x * blockDim.x + threadIdx.x;
    if (i < e) {
        int s = ei[i];
        int d = ei[e + i];
        g_srcs[atomicAdd(&g_cursor[d], 1)] = s;
    }
}

// ---------------------------------------------------------------------------
// GEMM: HS = (X @ W) * dinv[row]  -> fp16   (X: [n,64], W: [64,64])
// 256 threads, 128 rows/block, thread computes 8x4 micro-tile,
// k-loop unrolled x4 with float4 LDS on both operands.
// ---------------------------------------------------------------------------
__global__ void __launch_bounds__(256) k_gemm64(
        const float* __restrict__ X, const float* __restrict__ W,
        int n, int use_act) {
    __shared__ float  sW[64 * 64];                   // 16 KB
    __shared__ float4 sX4[128 * 16];                 // 32 KB (rows x 16 float4)
    const float* Xp = use_act ? g_act : X;
    int t = threadIdx.x;
    int n0 = blockIdx.x * 128;

#pragma unroll
    for (int i = 0; i < 16; i++) sW[t + 256 * i] = W[t + 256 * i];
    const float4* Xg4 = (const float4*)Xp;
#pragma unroll
    for (int i = 0; i < 8; i++) {
        int idx = t + 256 * i;                       // 0..2047
        int r = idx >> 4, c = idx & 15;
        sX4[idx] = (n0 + r < n) ? Xg4[(size_t)(n0 + r) * 16 + c]
                                : make_float4(0.f, 0.f, 0.f, 0.f);
    }
    __syncthreads();

    int tx = t & 15, ty = t >> 4;                    // cols 4*tx.., rows 8*ty..
    float acc[8][4];
#pragma unroll
    for (int i = 0; i < 8; i++)
#pragma unroll
        for (int j = 0; j < 4; j++) acc[i][j] = 0.0f;

#pragma unroll
    for (int k4 = 0; k4 < 16; k4++) {
        float4 w0 = *(const float4*)&sW[(k4 * 4 + 0) * 64 + tx * 4];
        float4 w1 = *(const float4*)&sW[(k4 * 4 + 1) * 64 + tx * 4];
        float4 w2 = *(const float4*)&sW[(k4 * 4 + 2) * 64 + tx * 4];
        float4 w3 = *(const float4*)&sW[(k4 * 4 + 3) * 64 + tx * 4];
#pragma unroll
        for (int i = 0; i < 8; i++) {
            float4 xv = sX4[(ty * 8 + i) * 16 + k4];
            acc[i][0] = fmaf(xv.x, w0.x, acc[i][0]);
            acc[i][1] = fmaf(xv.x, w0.y, acc[i][1]);
            acc[i][2] = fmaf(xv.x, w0.z, acc[i][2]);
            acc[i][3] = fmaf(xv.x, w0.w, acc[i][3]);
            acc[i][0] = fmaf(xv.y, w1.x, acc[i][0]);
            acc[i][1] = fmaf(xv.y, w1.y, acc[i][1]);
            acc[i][2] = fmaf(xv.y, w1.z, acc[i][2]);
            acc[i][3] = fmaf(xv.y, w1.w, acc[i][3]);
            acc[i][0] = fmaf(xv.z, w2.x, acc[i][0]);
            acc[i][1] = fmaf(xv.z, w2.y, acc[i][1]);
            acc[i][2] = fmaf(xv.z, w2.z, acc[i][2]);
            acc[i][3] = fmaf(xv.z, w2.w, acc[i][3]);
            acc[i][0] = fmaf(xv.w, w3.x, acc[i][0]);
            acc[i][1] = fmaf(xv.w, w3.y, acc[i][1]);
            acc[i][2] = fmaf(xv.w, w3.z, acc[i][2]);
            acc[i][3] = fmaf(xv.w, w3.w, acc[i][3]);
        }
    }

#pragma unroll
    for (int i = 0; i < 8; i++) {
        int r = n0 + ty * 8 + i;
        if (r < n) {
            float di = g_dinv[r];
            __half2 h0 = __floats2half2_rn(acc[i][0] * di, acc[i][1] * di);
            __half2 h1 = __floats2half2_rn(acc[i][2] * di, acc[i][3] * di);
            __half2* dst = (__half2*)&g_hs[(size_t)r * 64 + tx * 4];
            dst[0] = h0;
            dst[1] = h1;
        }
    }
}

// ---------------------------------------------------------------------------
// Fused gather + finalize:  act[d] = relu(dinv[d] * (hs[d] + sum_src hs[src]) + b)
// one warp per node; lane holds a half2 (2 feats) slice; fp32 accumulation
// ---------------------------------------------------------------------------
__global__ void k_gather(const float* __restrict__ bias, int n) {
    int warp = (blockIdx.x * blockDim.x + threadIdx.x) >> 5;
    if (warp >= n) return;
    int lane = threadIdx.x & 31;

    int start = g_start[warp];
    int deg   = g_count[warp];
    const int* __restrict__ srcs = g_srcs + start;
    const __half2* __restrict__ hs2 = (const __half2*)g_hs;

    float2 acc = __half22float2(hs2[(size_t)warp * 32 + lane]); // self-loop (hs[d])

    int j = 0;
    int end8 = deg & ~7;
    for (; j < end8; j += 8) {
        int s[8];
#pragma unroll
        for (int q = 0; q < 8; q++) s[q] = srcs[j + q];
        __half2 v[8];
#pragma unroll
        for (int q = 0; q < 8; q++) v[q] = hs2[(size_t)s[q] * 32 + lane];
#pragma unroll
        for (int q = 0; q < 8; q++) {
            float2 f = __half22float2(v[q]);
            acc.x += f.x;
            acc.y += f.y;
        }
    }
    for (; j < deg; j++) {
        float2 f = __half22float2(hs2[(size_t)srcs[j] * 32 + lane]);
        acc.x += f.x;
        acc.y += f.y;
    }

    float di = g_dinv[warp];
    float2 bv = ((const float2*)bias)[lane];
    float2 o;
    o.x = fmaxf(fmaf(acc.x, di, bv.x), 0.0f);
    o.y = fmaxf(fmaf(acc.y, di, bv.y), 0.0f);
    ((float2*)g_act)[(size_t)warp * 32 + lane] = o;
}

// ---------------------------------------------------------------------------
// FC head: out = act @ Wfc + bfc   (Wfc: [64,16])
// ---------------------------------------------------------------------------
__global__ void k_fc(const float* __restrict__ W, const float* __restrict__ b,
                     float* __restrict__ out, int n) {
    __shared__ float sW[64 * 16];
    __shared__ float sX[16 * 65];
    __shared__ float sB[16];
    int t = threadIdx.x;
    if (t < 16) sB[t] = b[t];
#pragma unroll
    for (int i = 0; i < 4; i++) sW[t + 256 * i] = W[t + 256 * i];
    int n0 = blockIdx.x * 16;
#pragma unroll
    for (int i = 0; i < 4; i++) {
        int idx = t + 256 * i;                       // 0..1023
        int r = idx >> 6, c = idx & 63;
        sX[r * 65 + c] = (n0 + r < n) ? g_act[(size_t)(n0 + r) * 64 + c] : 0.0f;
    }
    __syncthreads();

    int j = t & 15, r = t >> 4;
    float acc = sB[j];
#pragma unroll
    for (int k = 0; k < 64; k++)
        acc = fmaf(sX[r * 65 + k], sW[k * 16 + j], acc);
    int rg = n0 + r;
    if (rg < n) out[(size_t)rg * 16 + j] = acc;
}

// ---------------------------------------------------------------------------
extern "C" void kernel_launch(void* const* d_in, const int* in_sizes, int n_in,
                              void* d_out, int out_size) {
    const float* x   = (const float*)d_in[0];
    const int*   ei  = (const int*)d_in[1];   // int32 (JAX x64 disabled)
    const float* W1  = (const float*)d_in[2];
    const float* b1  = (const float*)d_in[3];
    const float* W2  = (const float*)d_in[4];
    const float* b2  = (const float*)d_in[5];
    const float* Wfc = (const float*)d_in[6];
    const float* bfc = (const float*)d_in[7];
    float* out = (float*)d_out;

    int n = in_sizes[0] / FEAT;
    int e = in_sizes[1] / 2;

    int nb_n  = (n + 255) / 256;
    int nb_e  = (e + 255) / 256;
    int nb_g  = (n + 127) / 128;
    int nb_s1 = (n + 1023) / 1024;               // scan blocks (<=128)
    int nb_ga = (int)(((long long)n * 32 + 255) / 256);
    int nb_fc = (n + 15) / 16;

    // CSR build (once, reused by both layers)
    k_zero <<<nb_n, 256>>>(n);
    k_hist <<<nb_e, 256>>>(ei, e);
    k_scan1<<<nb_s1, 1024>>>(n);
    k_scan3<<<nb_n, 256>>>(n, nb_s1);
    k_place<<<nb_e, 256>>>(ei, e);

    // Layer 1
    k_gemm64<<<nb_g, 256>>>(x, W1, n, 0);
    k_gather<<<nb_ga, 256>>>(b1, n);

    // Layer 2
    k_gemm64<<<nb_g, 256>>>(x, W2, n, 1);
    k_gather<<<nb_ga, 256>>>(b2, n);

    // FC head
    k_fc<<<nb_fc, 256>>>(Wfc, bfc, out, n);
}